// round 8
// baseline (speedup 1.0000x reference)
#include <cuda_runtime.h>
#include <cstdint>

#define NN 50000
#define DD 64
#define NE 800000
#define SLOTS 96          // bucket capacity per node (Poisson(16), +20 sigma)
#define OVF_CAP 4096      // overflow list capacity (expected use: 0)

// ---- scratch (__device__ globals; allocation-free rule) ----
// g_cnt: zero at entry of every call (zero-init on load; agg<RESET> restores).
__device__ int   g_cnt[NN];
__device__ int   g_slot[NN * SLOTS];   // bucket CSR: src nodes per dst
__device__ int   g_ovf_cnt;
__device__ int   g_ovf[2 * OVF_CAP];   // (dst, src) pairs
__device__ __align__(16) float g_t[NN * DD];   // t = act(X) @ W_nbr
__device__ __align__(16) float g_h[NN * DD];   // hidden activations

// ---------------------------------------------------------------------------
// Per-block int64-vs-int32 detection: sample the first 256 odd 32-bit words.
// int64 little-endian high halves (indices < 50000) are all zero; for int32
// they are real indices (P[all 256 zero] ~ (2e-5)^256 ~ 0).
// ---------------------------------------------------------------------------
__device__ __forceinline__ int detect_idx64(const unsigned* words) {
    __shared__ int nz;
    if (threadIdx.x == 0) nz = 0;
    __syncthreads();
    if (threadIdx.x < 256 && words[2 * threadIdx.x + 1] != 0u) nz = 1;
    __syncthreads();
    return nz ? 0 : 1;
}

__global__ void reset_ovf_kernel() {
    if (threadIdx.x == 0) g_ovf_cnt = 0;
}

// ---------------------------------------------------------------------------
// Bucket-CSR fill: one edge per thread (best measured point: high occupancy,
// one outstanding ATOMG per thread across many resident warps).
// ---------------------------------------------------------------------------
__global__ void __launch_bounds__(256) fill_kernel(const void* __restrict__ idx, int E) {
    int idx64 = detect_idx64((const unsigned*)idx);
    int e = blockIdx.x * blockDim.x + threadIdx.x;
    if (e >= E) return;
    int s, d;
    if (idx64) {
        const long long* p = (const long long*)idx;
        s = (int)p[e];
        d = (int)p[(size_t)E + e];
    } else {
        const int* p = (const int*)idx;
        s = p[e];
        d = p[(size_t)E + e];
    }
    int pos = atomicAdd(&g_cnt[d], 1);
    if (pos < SLOTS) {
        g_slot[d * SLOTS + pos] = s;
    } else {
        int o = atomicAdd(&g_ovf_cnt, 1);
        if (o < OVF_CAP) { g_ovf[2 * o] = d; g_ovf[2 * o + 1] = s; }
    }
}

// ---------------------------------------------------------------------------
// Dual GEMM: Omain = act(X)@Wroot + b ; Ot = act(X)@Wnbr
// 128 rows/block, 256 threads. Thread tile: 4 rows x 8 cols x 2 matrices.
// X staged TRANSPOSED (sXT[k][r], stride 132 -> every float4 read 16B-aligned).
// ---------------------------------------------------------------------------
#define XT_STRIDE 132

template <bool RELU>
__global__ void __launch_bounds__(256, 2) gemm_dual_kernel(
    const float* __restrict__ X,
    const float* __restrict__ Wroot,
    const float* __restrict__ Wnbr,
    const float* __restrict__ bias,
    float* __restrict__ Omain,
    float* __restrict__ Ot,
    int n)
{
    __shared__ __align__(16) float sWr[64 * 64];
    __shared__ __align__(16) float sWn[64 * 64];
    __shared__ __align__(16) float sB[64];
    __shared__ __align__(16) float sXT[64 * XT_STRIDE];   // [k][row]

    const int tid = threadIdx.x;
    const int row0 = blockIdx.x * 128;

    // stage weights (1024 float4 each -> 4 per thread)
    {
        const float4* wr4 = (const float4*)Wroot;
        const float4* wn4 = (const float4*)Wnbr;
        float4* swr4 = (float4*)sWr;
        float4* swn4 = (float4*)sWn;
#pragma unroll
        for (int i = 0; i < 4; i++) {
            swr4[tid + 256 * i] = wr4[tid + 256 * i];
            swn4[tid + 256 * i] = wn4[tid + 256 * i];
        }
        if (tid < 64) sB[tid] = bias[tid];
    }

    // stage X transposed: 128 rows x 16 float4-chunks = 2048 chunks, 8/thread
#pragma unroll
    for (int i = 0; i < 8; i++) {
        int idx = tid + 256 * i;      // 0..2047
        int r = idx >> 4;             // local row 0..127
        int c4 = idx & 15;            // float4 chunk 0..15
        int grow = row0 + r;
        float4 v = make_float4(0.f, 0.f, 0.f, 0.f);
        if (grow < n) v = ((const float4*)X)[(size_t)grow * 16 + c4];
        if (RELU) {
            v.x = fmaxf(v.x, 0.f); v.y = fmaxf(v.y, 0.f);
            v.z = fmaxf(v.z, 0.f); v.w = fmaxf(v.w, 0.f);
        }
        sXT[(c4 * 4 + 0) * XT_STRIDE + r] = v.x;
        sXT[(c4 * 4 + 1) * XT_STRIDE + r] = v.y;
        sXT[(c4 * 4 + 2) * XT_STRIDE + r] = v.z;
        sXT[(c4 * 4 + 3) * XT_STRIDE + r] = v.w;
    }
    __syncthreads();

    const int cseg = tid & 7;        // cols [cseg*8, cseg*8+8)
    const int rowgrp = tid >> 3;     // rows [rowgrp*4, rowgrp*4+4)

    float4 ar[4][2], an[4][2];
    {
        float4 b0 = *(const float4*)&sB[cseg * 8];
        float4 b1 = *(const float4*)&sB[cseg * 8 + 4];
#pragma unroll
        for (int j = 0; j < 4; j++) {
            ar[j][0] = b0; ar[j][1] = b1;
            an[j][0] = make_float4(0.f, 0.f, 0.f, 0.f);
            an[j][1] = make_float4(0.f, 0.f, 0.f, 0.f);
        }
    }

#pragma unroll 8
    for (int k = 0; k < 64; k++) {
        float4 xv = *(const float4*)&sXT[k * XT_STRIDE + rowgrp * 4];
        float4 wr0 = *(const float4*)&sWr[k * 64 + cseg * 8];
        float4 wr1 = *(const float4*)&sWr[k * 64 + cseg * 8 + 4];
        float4 wn0 = *(const float4*)&sWn[k * 64 + cseg * 8];
        float4 wn1 = *(const float4*)&sWn[k * 64 + cseg * 8 + 4];
        const float xs[4] = {xv.x, xv.y, xv.z, xv.w};
#pragma unroll
        for (int j = 0; j < 4; j++) {
            float xvj = xs[j];
            ar[j][0].x = fmaf(xvj, wr0.x, ar[j][0].x);
            ar[j][0].y = fmaf(xvj, wr0.y, ar[j][0].y);
            ar[j][0].z = fmaf(xvj, wr0.z, ar[j][0].z);
            ar[j][0].w = fmaf(xvj, wr0.w, ar[j][0].w);
            ar[j][1].x = fmaf(xvj, wr1.x, ar[j][1].x);
            ar[j][1].y = fmaf(xvj, wr1.y, ar[j][1].y);
            ar[j][1].z = fmaf(xvj, wr1.z, ar[j][1].z);
            ar[j][1].w = fmaf(xvj, wr1.w, ar[j][1].w);
            an[j][0].x = fmaf(xvj, wn0.x, an[j][0].x);
            an[j][0].y = fmaf(xvj, wn0.y, an[j][0].y);
            an[j][0].z = fmaf(xvj, wn0.z, an[j][0].z);
            an[j][0].w = fmaf(xvj, wn0.w, an[j][0].w);
            an[j][1].x = fmaf(xvj, wn1.x, an[j][1].x);
            an[j][1].y = fmaf(xvj, wn1.y, an[j][1].y);
            an[j][1].z = fmaf(xvj, wn1.z, an[j][1].z);
            an[j][1].w = fmaf(xvj, wn1.w, an[j][1].w);
        }
    }

#pragma unroll
    for (int j = 0; j < 4; j++) {
        int grow = row0 + rowgrp * 4 + j;
        if (grow < n) {
            float4* om = (float4*)(Omain + (size_t)grow * 64 + cseg * 8);
            om[0] = ar[j][0]; om[1] = ar[j][1];
            float4* ot = (float4*)(Ot + (size_t)grow * 64 + cseg * 8);
            ot[0] = an[j][0]; ot[1] = an[j][1];
        }
    }
}

// ---------------------------------------------------------------------------
// Bucket gather-aggregate: HALF-WARP per node, float4 per lane.
// out[i] += sum_j t[slot[i][j]].  RESET: restore g_cnt=0 for the next call.
// ---------------------------------------------------------------------------
template <bool RESET>
__global__ void __launch_bounds__(256) agg_kernel(
    const float* __restrict__ t, float* __restrict__ out, int n)
{
    int gid = blockIdx.x * blockDim.x + threadIdx.x;
    int node = gid >> 4;
    if (node >= n) return;
    int part = threadIdx.x & 15;

    int deg = g_cnt[node];
    if (deg > SLOTS) deg = SLOTS;
    const int* slots = &g_slot[node * SLOTS];

    const float4* t4 = (const float4*)t;
    float4 acc = make_float4(0.f, 0.f, 0.f, 0.f);

    int j = 0;
    for (; j + 4 <= deg; j += 4) {
        int s0 = __ldg(&slots[j]);
        int s1 = __ldg(&slots[j + 1]);
        int s2 = __ldg(&slots[j + 2]);
        int s3 = __ldg(&slots[j + 3]);
        float4 v0 = t4[(size_t)s0 * 16 + part];
        float4 v1 = t4[(size_t)s1 * 16 + part];
        float4 v2 = t4[(size_t)s2 * 16 + part];
        float4 v3 = t4[(size_t)s3 * 16 + part];
        acc.x += (v0.x + v1.x) + (v2.x + v3.x);
        acc.y += (v0.y + v1.y) + (v2.y + v3.y);
        acc.z += (v0.z + v1.z) + (v2.z + v3.z);
        acc.w += (v0.w + v1.w) + (v2.w + v3.w);
    }
    for (; j < deg; j++) {
        int s = __ldg(&slots[j]);
        float4 v = t4[(size_t)s * 16 + part];
        acc.x += v.x; acc.y += v.y; acc.z += v.z; acc.w += v.w;
    }

    float4* o4 = (float4*)out;
    float4 cur = o4[(size_t)node * 16 + part];
    cur.x += acc.x; cur.y += acc.y; cur.z += acc.z; cur.w += acc.w;
    o4[(size_t)node * 16 + part] = cur;

    if (RESET && part == 0) g_cnt[node] = 0;
}

// ---------------------------------------------------------------------------
// Overflow fixup: apply edges that exceeded SLOTS (expected count: 0).
// Runs after each agg; atomic adds are safe since the agg has completed.
// ---------------------------------------------------------------------------
__global__ void fixup_kernel(const float* __restrict__ t, float* __restrict__ out)
{
    int cnt = g_ovf_cnt;
    if (cnt > OVF_CAP) cnt = OVF_CAP;
    int total = cnt * 16;
    for (int i = blockIdx.x * blockDim.x + threadIdx.x; i < total;
         i += gridDim.x * blockDim.x) {
        int e = i >> 4, part = i & 15;
        int d = g_ovf[2 * e], s = g_ovf[2 * e + 1];
        float4 v = ((const float4*)(t + (size_t)s * 64))[part];
        float* dp = out + (size_t)d * 64 + part * 4;
        asm volatile("red.global.add.v4.f32 [%0], {%1, %2, %3, %4};"
                     :: "l"(dp), "f"(v.x), "f"(v.y), "f"(v.z), "f"(v.w)
                     : "memory");
    }
}

// ---------------------------------------------------------------------------
extern "C" void kernel_launch(void* const* d_in, const int* in_sizes, int n_in,
                              void* d_out, int out_size)
{
    const float* x      = (const float*)d_in[0];
    const void*  eidx   = d_in[1];
    const float* W1root = (const float*)d_in[2];
    const float* W1nbr  = (const float*)d_in[3];
    const float* b1     = (const float*)d_in[4];
    const float* W2root = (const float*)d_in[5];
    const float* W2nbr  = (const float*)d_in[6];
    const float* b2     = (const float*)d_in[7];
    float* out = (float*)d_out;

    const int n = in_sizes[0] / DD;     // 50000
    const int E = in_sizes[1] / 2;      // 800000

    float *hptr, *tptr;
    cudaGetSymbolAddress((void**)&hptr, g_h);
    cudaGetSymbolAddress((void**)&tptr, g_t);

    const int edge_blocks = (E + 255) / 256;
    const int gemm_blocks = (n + 127) / 128;
    const int agg_blocks  = (n * 16 + 255) / 256;

    // Side stream + events for graph-level parallelism (host-side resources
    // only; created once, reused — identical captured work every call).
    static cudaStream_t s_side = nullptr;
    static cudaEvent_t  ev_fork = nullptr, ev_join = nullptr;
    if (s_side == nullptr) {
        cudaStreamCreateWithFlags(&s_side, cudaStreamNonBlocking);
        cudaEventCreateWithFlags(&ev_fork, cudaEventDisableTiming);
        cudaEventCreateWithFlags(&ev_join, cudaEventDisableTiming);
    }

    // ---- fork: bucket-CSR build on side stream, concurrent with gemm1 ----
    cudaEventRecord(ev_fork, cudaStreamPerThread);
    cudaStreamWaitEvent(s_side, ev_fork, 0);

    reset_ovf_kernel<<<1, 32, 0, s_side>>>();
    fill_kernel<<<edge_blocks, 256, 0, s_side>>>(eidx, E);
    cudaEventRecord(ev_join, s_side);

    // ---- main stream: layer-1 GEMM in parallel with CSR build ----
    gemm_dual_kernel<false><<<gemm_blocks, 256>>>(x, W1root, W1nbr, b1, hptr, tptr, n);

    // join: agg1 needs both buckets and t1
    cudaStreamWaitEvent(cudaStreamPerThread, ev_join, 0);
    agg_kernel<false><<<agg_blocks, 256>>>(tptr, hptr, n);
    fixup_kernel<<<4, 256>>>(tptr, hptr);

    // ---- Layer 2 ----
    gemm_dual_kernel<true><<<gemm_blocks, 256>>>(hptr, W2root, W2nbr, b2, out, tptr, n);
    agg_kernel<true><<<agg_blocks, 256>>>(tptr, out, n);
    fixup_kernel<<<4, 256>>>(tptr, out);
}

// round 9
// speedup vs baseline: 1.1362x; 1.1362x over previous
#include <cuda_runtime.h>
#include <cuda_fp16.h>
#include <cstdint>

#define NN 50000
#define DD 64
#define NE 800000

// ---- scratch (__device__ globals; allocation-free rule) ----
__device__ int   g_csrc[NE];     // CSR: source node per edge, grouped by dst
__device__ int   g_deg[NN];      // invariant: zero at entry of every call
__device__ int   g_off[NN + 1];
__device__ int   g_cur[NN];
__device__ int   g_bsum[256];
__device__ int   g_done;         // invariant: zero at entry of every call
__device__ __align__(16) __half g_t[NN * DD];  // t = act(X) @ W_nbr  (fp16)
__device__ __align__(16) float  g_h[NN * DD];  // hidden activations  (fp32)

// ---------------------------------------------------------------------------
// Per-block int64-vs-int32 detection: sample the first 256 odd 32-bit words.
// int64 little-endian high halves (indices < 50000) are all zero; for int32
// they are real indices (P[all 256 zero] ~ (2e-5)^256 ~ 0).
// ---------------------------------------------------------------------------
__device__ __forceinline__ int detect_idx64(const unsigned* words) {
    __shared__ int nz;
    if (threadIdx.x == 0) nz = 0;
    __syncthreads();
    if (threadIdx.x < 256 && words[2 * threadIdx.x + 1] != 0u) nz = 1;
    __syncthreads();
    return nz ? 0 : 1;
}

// histogram of dst degrees (one edge per thread — best measured point)
__global__ void hist_kernel(const void* __restrict__ idx, int E) {
    int idx64 = detect_idx64((const unsigned*)idx);
    int i = blockIdx.x * blockDim.x + threadIdx.x;
    if (i >= E) return;
    int d;
    if (idx64) d = (int)((const long long*)idx)[(size_t)E + i];
    else       d = ((const int*)idx)[(size_t)E + i];
    atomicAdd(&g_deg[d], 1);
}

// ---- scan phase 1 (+ fused phase 2 via last-done block) ----
__global__ void scan1_kernel(int nblocks) {
    __shared__ int sh[256];
    int tid = threadIdx.x;
    int i = blockIdx.x * 256 + tid;
    int v = (i < NN) ? g_deg[i] : 0;
    sh[tid] = v;
    __syncthreads();
#pragma unroll
    for (int off = 1; off < 256; off <<= 1) {
        int x = (tid >= off) ? sh[tid - off] : 0;
        __syncthreads();
        sh[tid] += x;
        __syncthreads();
    }
    if (i < NN) g_off[i] = sh[tid] - v;          // exclusive within block
    if (tid == 255) g_bsum[blockIdx.x] = sh[255];

    // last-arriving block scans the block sums (exclusive) in-place
    __shared__ int is_last;
    __threadfence();
    if (tid == 0) is_last = (atomicAdd(&g_done, 1) == nblocks - 1) ? 1 : 0;
    __syncthreads();
    if (is_last) {
        int bv = (tid < nblocks) ? g_bsum[tid] : 0;
        sh[tid] = bv;
        __syncthreads();
#pragma unroll
        for (int off = 1; off < 256; off <<= 1) {
            int x = (tid >= off) ? sh[tid - off] : 0;
            __syncthreads();
            sh[tid] += x;
            __syncthreads();
        }
        if (tid < nblocks) g_bsum[tid] = sh[tid] - bv;
    }
}

// add block offsets; also restore g_deg=0 and g_done=0 for the next call
__global__ void scan3_kernel() {
    int i = blockIdx.x * 256 + threadIdx.x;
    if (i < NN) {
        int o = g_off[i] + g_bsum[blockIdx.x];
        g_off[i] = o;
        g_cur[i] = o;
        g_deg[i] = 0;
    }
    if (i == 0) { g_off[NN] = NE; g_done = 0; }
}

// fill CSR source list (one edge per thread)
__global__ void fill_kernel(const void* __restrict__ idx, int E) {
    int idx64 = detect_idx64((const unsigned*)idx);
    int e = blockIdx.x * blockDim.x + threadIdx.x;
    if (e >= E) return;
    int s, d;
    if (idx64) {
        const long long* p = (const long long*)idx;
        s = (int)p[e];
        d = (int)p[(size_t)E + e];
    } else {
        const int* p = (const int*)idx;
        s = p[e];
        d = p[(size_t)E + e];
    }
    int pos = atomicAdd(&g_cur[d], 1);
    g_csrc[pos] = s;
}

// ---------------------------------------------------------------------------
// Dual GEMM: Omain = act(X)@Wroot + b (fp32) ; Ot = act(X)@Wnbr (fp16)
// 128 rows/block, 256 threads. Thread tile: 4 rows x 8 cols x 2 matrices.
// X staged TRANSPOSED (sXT[k][r], stride 132 -> every float4 read 16B-aligned).
// ---------------------------------------------------------------------------
#define XT_STRIDE 132

template <bool RELU>
__global__ void __launch_bounds__(256, 2) gemm_dual_kernel(
    const float* __restrict__ X,
    const float* __restrict__ Wroot,
    const float* __restrict__ Wnbr,
    const float* __restrict__ bias,
    float* __restrict__ Omain,
    __half* __restrict__ Ot,
    int n)
{
    __shared__ __align__(16) float sWr[64 * 64];
    __shared__ __align__(16) float sWn[64 * 64];
    __shared__ __align__(16) float sB[64];
    __shared__ __align__(16) float sXT[64 * XT_STRIDE];   // [k][row]

    const int tid = threadIdx.x;
    const int row0 = blockIdx.x * 128;

    // stage weights (1024 float4 each -> 4 per thread)
    {
        const float4* wr4 = (const float4*)Wroot;
        const float4* wn4 = (const float4*)Wnbr;
        float4* swr4 = (float4*)sWr;
        float4* swn4 = (float4*)sWn;
#pragma unroll
        for (int i = 0; i < 4; i++) {
            swr4[tid + 256 * i] = wr4[tid + 256 * i];
            swn4[tid + 256 * i] = wn4[tid + 256 * i];
        }
        if (tid < 64) sB[tid] = bias[tid];
    }

    // stage X transposed: 128 rows x 16 float4-chunks = 2048 chunks, 8/thread
#pragma unroll
    for (int i = 0; i < 8; i++) {
        int idx = tid + 256 * i;      // 0..2047
        int r = idx >> 4;             // local row 0..127
        int c4 = idx & 15;            // float4 chunk 0..15
        int grow = row0 + r;
        float4 v = make_float4(0.f, 0.f, 0.f, 0.f);
        if (grow < n) v = ((const float4*)X)[(size_t)grow * 16 + c4];
        if (RELU) {
            v.x = fmaxf(v.x, 0.f); v.y = fmaxf(v.y, 0.f);
            v.z = fmaxf(v.z, 0.f); v.w = fmaxf(v.w, 0.f);
        }
        sXT[(c4 * 4 + 0) * XT_STRIDE + r] = v.x;
        sXT[(c4 * 4 + 1) * XT_STRIDE + r] = v.y;
        sXT[(c4 * 4 + 2) * XT_STRIDE + r] = v.z;
        sXT[(c4 * 4 + 3) * XT_STRIDE + r] = v.w;
    }
    __syncthreads();

    const int cseg = tid & 7;        // cols [cseg*8, cseg*8+8)
    const int rowgrp = tid >> 3;     // rows [rowgrp*4, rowgrp*4+4)

    float4 ar[4][2], an[4][2];
    {
        float4 b0 = *(const float4*)&sB[cseg * 8];
        float4 b1 = *(const float4*)&sB[cseg * 8 + 4];
#pragma unroll
        for (int j = 0; j < 4; j++) {
            ar[j][0] = b0; ar[j][1] = b1;
            an[j][0] = make_float4(0.f, 0.f, 0.f, 0.f);
            an[j][1] = make_float4(0.f, 0.f, 0.f, 0.f);
        }
    }

#pragma unroll 8
    for (int k = 0; k < 64; k++) {
        float4 xv = *(const float4*)&sXT[k * XT_STRIDE + rowgrp * 4];
        float4 wr0 = *(const float4*)&sWr[k * 64 + cseg * 8];
        float4 wr1 = *(const float4*)&sWr[k * 64 + cseg * 8 + 4];
        float4 wn0 = *(const float4*)&sWn[k * 64 + cseg * 8];
        float4 wn1 = *(const float4*)&sWn[k * 64 + cseg * 8 + 4];
        const float xs[4] = {xv.x, xv.y, xv.z, xv.w};
#pragma unroll
        for (int j = 0; j < 4; j++) {
            float xvj = xs[j];
            ar[j][0].x = fmaf(xvj, wr0.x, ar[j][0].x);
            ar[j][0].y = fmaf(xvj, wr0.y, ar[j][0].y);
            ar[j][0].z = fmaf(xvj, wr0.z, ar[j][0].z);
            ar[j][0].w = fmaf(xvj, wr0.w, ar[j][0].w);
            ar[j][1].x = fmaf(xvj, wr1.x, ar[j][1].x);
            ar[j][1].y = fmaf(xvj, wr1.y, ar[j][1].y);
            ar[j][1].z = fmaf(xvj, wr1.z, ar[j][1].z);
            ar[j][1].w = fmaf(xvj, wr1.w, ar[j][1].w);
            an[j][0].x = fmaf(xvj, wn0.x, an[j][0].x);
            an[j][0].y = fmaf(xvj, wn0.y, an[j][0].y);
            an[j][0].z = fmaf(xvj, wn0.z, an[j][0].z);
            an[j][0].w = fmaf(xvj, wn0.w, an[j][0].w);
            an[j][1].x = fmaf(xvj, wn1.x, an[j][1].x);
            an[j][1].y = fmaf(xvj, wn1.y, an[j][1].y);
            an[j][1].z = fmaf(xvj, wn1.z, an[j][1].z);
            an[j][1].w = fmaf(xvj, wn1.w, an[j][1].w);
        }
    }

#pragma unroll
    for (int j = 0; j < 4; j++) {
        int grow = row0 + rowgrp * 4 + j;
        if (grow < n) {
            float4* om = (float4*)(Omain + (size_t)grow * 64 + cseg * 8);
            om[0] = ar[j][0]; om[1] = ar[j][1];
            // fp16 pack: 8 cols -> 4 half2 -> one 16B store
            __half2 hp[4];
            hp[0] = __floats2half2_rn(an[j][0].x, an[j][0].y);
            hp[1] = __floats2half2_rn(an[j][0].z, an[j][0].w);
            hp[2] = __floats2half2_rn(an[j][1].x, an[j][1].y);
            hp[3] = __floats2half2_rn(an[j][1].z, an[j][1].w);
            *(uint4*)(Ot + (size_t)grow * 64 + cseg * 8) = *(uint4*)hp;
        }
    }
}

// ---------------------------------------------------------------------------
// CSR gather-aggregate (fp16 t): 8 lanes per node, 16B (8 halves) per lane.
// out[i] += sum_{e: dst==i} t[csrc[e]]  — fp32 accumulate.
// 4 nodes per warp, unroll-4 => high MLP at half the load-instruction count.
// ---------------------------------------------------------------------------
__global__ void __launch_bounds__(256) agg_kernel(
    const __half* __restrict__ t, float* __restrict__ out, int n)
{
    int gid = blockIdx.x * blockDim.x + threadIdx.x;
    int node = gid >> 3;
    if (node >= n) return;
    int part = threadIdx.x & 7;          // 8 x 16B = 128B fp16 row

    int start = g_off[node];
    int end   = g_off[node + 1];

    const uint4* tH = (const uint4*)t;   // row = 8 uint4
    float acc[8] = {0.f, 0.f, 0.f, 0.f, 0.f, 0.f, 0.f, 0.f};

    int j = start;
    for (; j + 4 <= end; j += 4) {
        int s0 = __ldg(&g_csrc[j]);
        int s1 = __ldg(&g_csrc[j + 1]);
        int s2 = __ldg(&g_csrc[j + 2]);
        int s3 = __ldg(&g_csrc[j + 3]);
        uint4 r0 = tH[(size_t)s0 * 8 + part];
        uint4 r1 = tH[(size_t)s1 * 8 + part];
        uint4 r2 = tH[(size_t)s2 * 8 + part];
        uint4 r3 = tH[(size_t)s3 * 8 + part];
        const uint4 rr[4] = {r0, r1, r2, r3};
#pragma unroll
        for (int q = 0; q < 4; q++) {
            const __half2* hp = (const __half2*)&rr[q];
#pragma unroll
            for (int c = 0; c < 4; c++) {
                float2 f = __half22float2(hp[c]);
                acc[2 * c]     += f.x;
                acc[2 * c + 1] += f.y;
            }
        }
    }
    for (; j < end; j++) {
        int s = __ldg(&g_csrc[j]);
        uint4 r = tH[(size_t)s * 8 + part];
        const __half2* hp = (const __half2*)&r;
#pragma unroll
        for (int c = 0; c < 4; c++) {
            float2 f = __half22float2(hp[c]);
            acc[2 * c]     += f.x;
            acc[2 * c + 1] += f.y;
        }
    }

    float4* o4 = (float4*)(out + (size_t)node * 64 + part * 8);
    float4 c0 = o4[0], c1 = o4[1];
    c0.x += acc[0]; c0.y += acc[1]; c0.z += acc[2]; c0.w += acc[3];
    c1.x += acc[4]; c1.y += acc[5]; c1.z += acc[6]; c1.w += acc[7];
    o4[0] = c0; o4[1] = c1;
}

// ---------------------------------------------------------------------------
extern "C" void kernel_launch(void* const* d_in, const int* in_sizes, int n_in,
                              void* d_out, int out_size)
{
    const float* x      = (const float*)d_in[0];
    const void*  eidx   = d_in[1];
    const float* W1root = (const float*)d_in[2];
    const float* W1nbr  = (const float*)d_in[3];
    const float* b1     = (const float*)d_in[4];
    const float* W2root = (const float*)d_in[5];
    const float* W2nbr  = (const float*)d_in[6];
    const float* b2     = (const float*)d_in[7];
    float* out = (float*)d_out;

    const int n = in_sizes[0] / DD;     // 50000
    const int E = in_sizes[1] / 2;      // 800000

    float* hptr;
    __half* tptr;
    cudaGetSymbolAddress((void**)&hptr, g_h);
    cudaGetSymbolAddress((void**)&tptr, g_t);

    const int edge_blocks = (E + 255) / 256;
    const int scan_blocks = (n + 255) / 256;          // 196
    const int gemm_blocks = (n + 127) / 128;
    const int agg_blocks  = (n * 8 + 255) / 256;

    // Side stream + events for graph-level parallelism (host-side resources
    // only; created once, reused — identical captured work every call).
    static cudaStream_t s_side = nullptr;
    static cudaEvent_t  ev_fork = nullptr, ev_join = nullptr;
    if (s_side == nullptr) {
        cudaStreamCreateWithFlags(&s_side, cudaStreamNonBlocking);
        cudaEventCreateWithFlags(&ev_fork, cudaEventDisableTiming);
        cudaEventCreateWithFlags(&ev_join, cudaEventDisableTiming);
    }

    // ---- fork: CSR build on side stream, concurrent with gemm1 ----
    cudaEventRecord(ev_fork, cudaStreamPerThread);
    cudaStreamWaitEvent(s_side, ev_fork, 0);

    hist_kernel <<<edge_blocks, 256, 0, s_side>>>(eidx, E);
    scan1_kernel<<<scan_blocks, 256, 0, s_side>>>(scan_blocks);
    scan3_kernel<<<scan_blocks, 256, 0, s_side>>>();
    fill_kernel <<<edge_blocks, 256, 0, s_side>>>(eidx, E);
    cudaEventRecord(ev_join, s_side);

    // ---- main stream: layer-1 GEMM in parallel with CSR build ----
    gemm_dual_kernel<false><<<gemm_blocks, 256>>>(x, W1root, W1nbr, b1, hptr, tptr, n);

    // join: agg1 needs both CSR and t1
    cudaStreamWaitEvent(cudaStreamPerThread, ev_join, 0);
    agg_kernel<<<agg_blocks, 256>>>(tptr, hptr, n);

    // ---- Layer 2 ----
    gemm_dual_kernel<true><<<gemm_blocks, 256>>>(hptr, W2root, W2nbr, b2, out, tptr, n);
    agg_kernel<<<agg_blocks, 256>>>(tptr, out, n);
}

// round 10
// speedup vs baseline: 1.7566x; 1.5461x over previous
#include <cuda_runtime.h>
#include <cuda_fp16.h>
#include <cstdint>

#define NN 50000
#define DD 64
#define NE 800000

// ---- scratch (__device__ globals; allocation-free rule) ----
__device__ int   g_csrc[NE];     // CSR: source node per edge, grouped by dst
__device__ int   g_deg[NN];      // invariant: zero at entry of every call
__device__ int   g_off[NN + 1];
__device__ int   g_cur[NN];
__device__ int   g_bsum[256];
__device__ int   g_done;         // invariant: zero at entry of every call
__device__ __align__(16) __half g_t[NN * DD];  // t = act(X) @ W_nbr  (fp16)
__device__ __align__(16) float  g_h[NN * DD];  // hidden activations  (fp32)

// ---------------------------------------------------------------------------
// Per-block int64-vs-int32 detection (odd 32-bit words all zero => int64).
// ---------------------------------------------------------------------------
__device__ __forceinline__ int detect_idx64(const unsigned* words) {
    __shared__ int nz;
    if (threadIdx.x == 0) nz = 0;
    __syncthreads();
    if (threadIdx.x < 256 && words[2 * threadIdx.x + 1] != 0u) nz = 1;
    __syncthreads();
    return nz ? 0 : 1;
}

__global__ void hist_kernel(const void* __restrict__ idx, int E) {
    int idx64 = detect_idx64((const unsigned*)idx);
    int i = blockIdx.x * blockDim.x + threadIdx.x;
    if (i >= E) return;
    int d;
    if (idx64) d = (int)((const long long*)idx)[(size_t)E + i];
    else       d = ((const int*)idx)[(size_t)E + i];
    atomicAdd(&g_deg[d], 1);
}

// ---- scan phase 1 (+ fused phase 2 via last-done block) ----
__global__ void scan1_kernel(int nblocks) {
    __shared__ int sh[256];
    int tid = threadIdx.x;
    int i = blockIdx.x * 256 + tid;
    int v = (i < NN) ? g_deg[i] : 0;
    sh[tid] = v;
    __syncthreads();
#pragma unroll
    for (int off = 1; off < 256; off <<= 1) {
        int x = (tid >= off) ? sh[tid - off] : 0;
        __syncthreads();
        sh[tid] += x;
        __syncthreads();
    }
    if (i < NN) g_off[i] = sh[tid] - v;
    if (tid == 255) g_bsum[blockIdx.x] = sh[255];

    __shared__ int is_last;
    __threadfence();
    if (tid == 0) is_last = (atomicAdd(&g_done, 1) == nblocks - 1) ? 1 : 0;
    __syncthreads();
    if (is_last) {
        int bv = (tid < nblocks) ? g_bsum[tid] : 0;
        sh[tid] = bv;
        __syncthreads();
#pragma unroll
        for (int off = 1; off < 256; off <<= 1) {
            int x = (tid >= off) ? sh[tid - off] : 0;
            __syncthreads();
            sh[tid] += x;
            __syncthreads();
        }
        if (tid < nblocks) g_bsum[tid] = sh[tid] - bv;
    }
}

__global__ void scan3_kernel() {
    int i = blockIdx.x * 256 + threadIdx.x;
    if (i < NN) {
        int o = g_off[i] + g_bsum[blockIdx.x];
        g_off[i] = o;
        g_cur[i] = o;
        g_deg[i] = 0;
    }
    if (i == 0) { g_off[NN] = NE; g_done = 0; }
}

__global__ void fill_kernel(const void* __restrict__ idx, int E) {
    int idx64 = detect_idx64((const unsigned*)idx);
    int e = blockIdx.x * blockDim.x + threadIdx.x;
    if (e >= E) return;
    int s, d;
    if (idx64) {
        const long long* p = (const long long*)idx;
        s = (int)p[e];
        d = (int)p[(size_t)E + e];
    } else {
        const int* p = (const int*)idx;
        s = p[e];
        d = p[(size_t)E + e];
    }
    int pos = atomicAdd(&g_cur[d], 1);
    g_csrc[pos] = s;
}

// ---------------------------------------------------------------------------
// Dual GEMM via mma.sync.m16n8k16 (fp16 in, fp32 acc).
// Block: 128 M-rows, 256 threads (8 warps = 4m x 2n; warp tile 32x64).
// B = [Wroot | Wnbr] staged as 64x128 fp16. warp_n==0 -> Omain (fp32 + bias),
// warp_n==1 -> Ot (fp16). SMEM XOR-swizzled (16B chunk ^ (row&7)) for
// conflict-free ldmatrix.
// ---------------------------------------------------------------------------
__device__ __forceinline__ uint32_t smem_u32(const void* p) {
    return (uint32_t)__cvta_generic_to_shared(p);
}

__device__ __forceinline__ void ldm_x4(uint32_t* r, uint32_t addr) {
    asm volatile("ldmatrix.sync.aligned.m8n8.x4.shared.b16 {%0,%1,%2,%3}, [%4];"
                 : "=r"(r[0]), "=r"(r[1]), "=r"(r[2]), "=r"(r[3]) : "r"(addr));
}
__device__ __forceinline__ void ldm_x4_t(uint32_t* r, uint32_t addr) {
    asm volatile("ldmatrix.sync.aligned.m8n8.x4.trans.shared.b16 {%0,%1,%2,%3}, [%4];"
                 : "=r"(r[0]), "=r"(r[1]), "=r"(r[2]), "=r"(r[3]) : "r"(addr));
}
__device__ __forceinline__ void mma16816(float* c, const uint32_t* a,
                                         uint32_t b0, uint32_t b1) {
    asm volatile(
        "mma.sync.aligned.m16n8k16.row.col.f32.f16.f16.f32 "
        "{%0,%1,%2,%3}, {%4,%5,%6,%7}, {%8,%9}, {%0,%1,%2,%3};"
        : "+f"(c[0]), "+f"(c[1]), "+f"(c[2]), "+f"(c[3])
        : "r"(a[0]), "r"(a[1]), "r"(a[2]), "r"(a[3]), "r"(b0), "r"(b1));
}

template <bool RELU>
__global__ void __launch_bounds__(256) gemm_dual_kernel(
    const float* __restrict__ X,
    const float* __restrict__ Wroot,
    const float* __restrict__ Wnbr,
    const float* __restrict__ bias,
    float* __restrict__ Omain,
    __half* __restrict__ Ot,
    int n)
{
    __shared__ __align__(16) __half sX[128 * 64];    // row stride 64h = 8 chunks
    __shared__ __align__(16) __half sW[64 * 128];    // row stride 128h = 16 chunks
    __shared__ float sBias[64];

    const int tid = threadIdx.x;
    const int row0 = blockIdx.x * 128;

    // ---- stage X (fp32 -> fp16, optional relu, swizzled): 1024 chunks ----
#pragma unroll
    for (int i = 0; i < 4; i++) {
        int idx = tid + 256 * i;          // 0..1023
        int r = idx >> 3;                 // local row 0..127
        int c8 = idx & 7;                 // 16B chunk 0..7
        int grow = row0 + r;
        float4 v0 = make_float4(0.f, 0.f, 0.f, 0.f), v1 = v0;
        if (grow < n) {
            const float4* xr = (const float4*)X + (size_t)grow * 16;
            v0 = xr[c8 * 2]; v1 = xr[c8 * 2 + 1];
        }
        if (RELU) {
            v0.x = fmaxf(v0.x, 0.f); v0.y = fmaxf(v0.y, 0.f);
            v0.z = fmaxf(v0.z, 0.f); v0.w = fmaxf(v0.w, 0.f);
            v1.x = fmaxf(v1.x, 0.f); v1.y = fmaxf(v1.y, 0.f);
            v1.z = fmaxf(v1.z, 0.f); v1.w = fmaxf(v1.w, 0.f);
        }
        __half2 hp[4];
        hp[0] = __floats2half2_rn(v0.x, v0.y);
        hp[1] = __floats2half2_rn(v0.z, v0.w);
        hp[2] = __floats2half2_rn(v1.x, v1.y);
        hp[3] = __floats2half2_rn(v1.z, v1.w);
        *(uint4*)&sX[r * 64 + ((c8 ^ (r & 7)) << 3)] = *(uint4*)hp;
    }

    // ---- stage W = [Wroot | Wnbr] (64 rows x 16 chunks, swizzled) ----
#pragma unroll
    for (int i = 0; i < 4; i++) {
        int idx = tid + 256 * i;          // 0..1023
        int k = idx >> 4;                 // 0..63
        int c16 = idx & 15;               // chunk 0..15
        const float* src = (c16 < 8) ? (Wroot + k * 64 + c16 * 8)
                                     : (Wnbr + k * 64 + (c16 - 8) * 8);
        float4 v0 = ((const float4*)src)[0];
        float4 v1 = ((const float4*)src)[1];
        __half2 hp[4];
        hp[0] = __floats2half2_rn(v0.x, v0.y);
        hp[1] = __floats2half2_rn(v0.z, v0.w);
        hp[2] = __floats2half2_rn(v1.x, v1.y);
        hp[3] = __floats2half2_rn(v1.z, v1.w);
        *(uint4*)&sW[k * 128 + ((c16 ^ (k & 7)) << 3)] = *(uint4*)hp;
    }
    if (tid < 64) sBias[tid] = bias[tid];
    __syncthreads();

    // ---- mma phase ----
    const int lane = tid & 31;
    const int wid = tid >> 5;
    const int warp_m = wid & 3;          // 0..3 -> m 32-row slab
    const int warp_n = wid >> 2;         // 0: Omain cols 0-63, 1: Ot
    const int m_base = warp_m * 32;
    const int n_base = warp_n * 64;

    float c[2][8][4];
#pragma unroll
    for (int tm = 0; tm < 2; tm++)
#pragma unroll
        for (int nt = 0; nt < 8; nt++)
#pragma unroll
            for (int q = 0; q < 4; q++) c[tm][nt][q] = 0.f;

    const uint32_t sX_base = smem_u32(sX);
    const uint32_t sW_base = smem_u32(sW);

#pragma unroll
    for (int ks = 0; ks < 4; ks++) {
        uint32_t a[2][4];
#pragma unroll
        for (int tm = 0; tm < 2; tm++) {
            int rl = m_base + tm * 16 + (lane & 15);
            int kchunk = ks * 2 + (lane >> 4);
            uint32_t off = rl * 64 + ((kchunk ^ (rl & 7)) << 3);
            ldm_x4(a[tm], sX_base + off * 2);
        }
        uint32_t b[4][4];
#pragma unroll
        for (int np = 0; np < 4; np++) {
            int rk = ks * 16 + (lane & 15);
            int nchunk = (n_base >> 3) + np * 2 + (lane >> 4);
            uint32_t off = rk * 128 + ((nchunk ^ (rk & 7)) << 3);
            ldm_x4_t(b[np], sW_base + off * 2);
        }
#pragma unroll
        for (int tm = 0; tm < 2; tm++)
#pragma unroll
            for (int np = 0; np < 4; np++) {
                mma16816(c[tm][2 * np],     a[tm], b[np][0], b[np][1]);
                mma16816(c[tm][2 * np + 1], a[tm], b[np][2], b[np][3]);
            }
    }

    // ---- epilogue ----
    const int groupID = lane >> 2;
    const int tq = lane & 3;
#pragma unroll
    for (int tm = 0; tm < 2; tm++) {
#pragma unroll
        for (int nt = 0; nt < 8; nt++) {
            int col = nt * 8 + tq * 2;               // within this warp's 64 cols
            int r0g = row0 + m_base + tm * 16 + groupID;
            int r1g = r0g + 8;
            if (warp_n == 0) {
                float2 bv = *(float2*)&sBias[col];
                if (r0g < n) {
                    float2 o = make_float2(c[tm][nt][0] + bv.x, c[tm][nt][1] + bv.y);
                    *(float2*)(Omain + (size_t)r0g * 64 + col) = o;
                }
                if (r1g < n) {
                    float2 o = make_float2(c[tm][nt][2] + bv.x, c[tm][nt][3] + bv.y);
                    *(float2*)(Omain + (size_t)r1g * 64 + col) = o;
                }
            } else {
                if (r0g < n)
                    *(__half2*)(Ot + (size_t)r0g * 64 + col) =
                        __floats2half2_rn(c[tm][nt][0], c[tm][nt][1]);
                if (r1g < n)
                    *(__half2*)(Ot + (size_t)r1g * 64 + col) =
                        __floats2half2_rn(c[tm][nt][2], c[tm][nt][3]);
            }
        }
    }
}

// ---------------------------------------------------------------------------
// CSR gather-aggregate (fp16 t): 8 lanes per node, 16B (8 halves) per lane.
// out[i] += sum_{e: dst==i} t[csrc[e]]  — fp32 accumulate.
// ---------------------------------------------------------------------------
__global__ void __launch_bounds__(256) agg_kernel(
    const __half* __restrict__ t, float* __restrict__ out, int n)
{
    int gid = blockIdx.x * blockDim.x + threadIdx.x;
    int node = gid >> 3;
    if (node >= n) return;
    int part = threadIdx.x & 7;

    int start = g_off[node];
    int end   = g_off[node + 1];

    const uint4* tH = (const uint4*)t;
    float acc[8] = {0.f, 0.f, 0.f, 0.f, 0.f, 0.f, 0.f, 0.f};

    int j = start;
    for (; j + 4 <= end; j += 4) {
        int s0 = __ldg(&g_csrc[j]);
        int s1 = __ldg(&g_csrc[j + 1]);
        int s2 = __ldg(&g_csrc[j + 2]);
        int s3 = __ldg(&g_csrc[j + 3]);
        uint4 r0 = tH[(size_t)s0 * 8 + part];
        uint4 r1 = tH[(size_t)s1 * 8 + part];
        uint4 r2 = tH[(size_t)s2 * 8 + part];
        uint4 r3 = tH[(size_t)s3 * 8 + part];
        const uint4 rr[4] = {r0, r1, r2, r3};
#pragma unroll
        for (int q = 0; q < 4; q++) {
            const __half2* hp = (const __half2*)&rr[q];
#pragma unroll
            for (int cidx = 0; cidx < 4; cidx++) {
                float2 f = __half22float2(hp[cidx]);
                acc[2 * cidx]     += f.x;
                acc[2 * cidx + 1] += f.y;
            }
        }
    }
    for (; j < end; j++) {
        int s = __ldg(&g_csrc[j]);
        uint4 r = tH[(size_t)s * 8 + part];
        const __half2* hp = (const __half2*)&r;
#pragma unroll
        for (int cidx = 0; cidx < 4; cidx++) {
            float2 f = __half22float2(hp[cidx]);
            acc[2 * cidx]     += f.x;
            acc[2 * cidx + 1] += f.y;
        }
    }

    float4* o4 = (float4*)(out + (size_t)node * 64 + part * 8);
    float4 c0 = o4[0], c1 = o4[1];
    c0.x += acc[0]; c0.y += acc[1]; c0.z += acc[2]; c0.w += acc[3];
    c1.x += acc[4]; c1.y += acc[5]; c1.z += acc[6]; c1.w += acc[7];
    o4[0] = c0; o4[1] = c1;
}

// ---------------------------------------------------------------------------
extern "C" void kernel_launch(void* const* d_in, const int* in_sizes, int n_in,
                              void* d_out, int out_size)
{
    const float* x      = (const float*)d_in[0];
    const void*  eidx   = d_in[1];
    const float* W1root = (const float*)d_in[2];
    const float* W1nbr  = (const float*)d_in[3];
    const float* b1     = (const float*)d_in[4];
    const float* W2root = (const float*)d_in[5];
    const float* W2nbr  = (const float*)d_in[6];
    const float* b2     = (const float*)d_in[7];
    float* out = (float*)d_out;

    const int n = in_sizes[0] / DD;     // 50000
    const int E = in_sizes[1] / 2;      // 800000

    float* hptr;
    __half* tptr;
    cudaGetSymbolAddress((void**)&hptr, g_h);
    cudaGetSymbolAddress((void**)&tptr, g_t);

    const int edge_blocks = (E + 255) / 256;
    const int scan_blocks = (n + 255) / 256;          // 196
    const int gemm_blocks = (n + 127) / 128;
    const int agg_blocks  = (n * 8 + 255) / 256;

    static cudaStream_t s_side = nullptr;
    static cudaEvent_t  ev_fork = nullptr, ev_join = nullptr;
    if (s_side == nullptr) {
        cudaStreamCreateWithFlags(&s_side, cudaStreamNonBlocking);
        cudaEventCreateWithFlags(&ev_fork, cudaEventDisableTiming);
        cudaEventCreateWithFlags(&ev_join, cudaEventDisableTiming);
    }

    // ---- fork: CSR build on side stream, concurrent with gemm1 ----
    cudaEventRecord(ev_fork, cudaStreamPerThread);
    cudaStreamWaitEvent(s_side, ev_fork, 0);

    hist_kernel <<<edge_blocks, 256, 0, s_side>>>(eidx, E);
    scan1_kernel<<<scan_blocks, 256, 0, s_side>>>(scan_blocks);
    scan3_kernel<<<scan_blocks, 256, 0, s_side>>>();
    fill_kernel <<<edge_blocks, 256, 0, s_side>>>(eidx, E);
    cudaEventRecord(ev_join, s_side);

    // ---- main stream: layer-1 GEMM in parallel with CSR build ----
    gemm_dual_kernel<false><<<gemm_blocks, 256>>>(x, W1root, W1nbr, b1, hptr, tptr, n);

    // join: agg1 needs both CSR and t1
    cudaStreamWaitEvent(cudaStreamPerThread, ev_join, 0);
    agg_kernel<<<agg_blocks, 256>>>(tptr, hptr, n);

    // ---- Layer 2 ----
    gemm_dual_kernel<true><<<gemm_blocks, 256>>>(hptr, W2root, W2nbr, b2, out, tptr, n);
    agg_kernel<<<agg_blocks, 256>>>(tptr, out, n);
}